// round 15
// baseline (speedup 1.0000x reference)
#include <cuda_runtime.h>
#include <math.h>
#include <stdint.h>

#define NROWS 100000
#define DIMS  1443
#define NB    148
#define NT    512
#define NWARP 16
#define GSTRIDE (NB*NT)
#define WPP   (37*NWARP)        // 592 warps per phase (gather)
#define JROWS 25000
#define SCAP  1024
#define NGRP  782               // ceil(25000/32) row-groups per phase
#define GW4   148               // GEMV warps per phase (37 blocks x 4)
#define SROW  188               // padded stage row stride (floats), 47*4 -> conflict-free
#define STAGEF (32*SROW)        // 6016 floats per stage
#define CHUNKB 720              // bytes copied per lane per tile (180 floats)
#define TILETX (32*CHUNKB)      // 23040
#define WOFF  1444
#define WS_FLOATS (3*WOFF)      // 4332 (17328 B, 16B-aligned)
#define DSMEM ((WS_FLOATS + 8*STAGEF) * 4)   // 209840 B

// ---------------- device scratch (allocation-free) ----------------
__device__ unsigned g_bar = 0;
__device__ float    g_y1[NROWS], g_y2[NROWS], g_y3[NROWS];
__device__ float    g_prod[NROWS];
__device__ float    g_coef[NROWS];
__device__ unsigned g_key[NROWS];
__device__ unsigned g_hist[3][65536];     // zeroed in C4 of its round (replay invariant)
__device__ unsigned g_hist8[3][256];
__device__ unsigned g_candk[NROWS];
__device__ int      g_candr[NROWS];
__device__ int      g_ncand3[3];
__device__ float    g_fpart[NB][DIMS];

__device__ __forceinline__ unsigned f2key(float f) {
    unsigned u = __float_as_uint(f);
    return (u & 0x80000000u) ? ~u : (u | 0x80000000u);
}
__device__ __forceinline__ uint32_t s2u(const void* p) {
    uint32_t a;
    asm("{ .reg .u64 t; cvta.to.shared.u64 t, %1; cvt.u32.u64 %0, t; }"
        : "=r"(a) : "l"(p));
    return a;
}
__device__ __forceinline__ void mb_init(uint32_t m, uint32_t c) {
    asm volatile("mbarrier.init.shared.b64 [%0], %1;" :: "r"(m), "r"(c) : "memory");
}
__device__ __forceinline__ void mb_extx(uint32_t m, uint32_t b) {
    asm volatile("mbarrier.arrive.expect_tx.shared.b64 _, [%0], %1;"
                 :: "r"(m), "r"(b) : "memory");
}
__device__ __forceinline__ void bulk_g2s(uint32_t dst, const void* src,
                                         uint32_t bytes, uint32_t m) {
    asm volatile("cp.async.bulk.shared::cta.global.mbarrier::complete_tx::bytes "
                 "[%0], [%1], %2, [%3];"
                 :: "r"(dst), "l"(src), "r"(bytes), "r"(m) : "memory");
}
__device__ __forceinline__ void mb_wait(uint32_t m, uint32_t par) {
    uint32_t done;
    asm volatile(
        "{ .reg .pred p; mbarrier.try_wait.parity.acquire.cta.shared::cta.b64 "
        "p, [%1], %2; selp.b32 %0,1,0,p; }"
        : "=r"(done) : "r"(m), "r"(par) : "memory");
    while (!done) {
        asm volatile(
            "{ .reg .pred p; mbarrier.try_wait.parity.acquire.cta.shared::cta.b64 "
            "p, [%1], %2, 0x989680; selp.b32 %0,1,0,p; }"
            : "=r"(done) : "r"(m), "r"(par) : "memory");
    }
}
__device__ __forceinline__ void fence_async() {
    asm volatile("fence.proxy.async.shared::cta;" ::: "memory");
}

// grid barrier: arrive via atomicAdd, spin on plain volatile load
__device__ __forceinline__ void gbar(unsigned ph) {
    __syncthreads();
    if (threadIdx.x == 0) {
        __threadfence();
        atomicAdd(&g_bar, 1u);
        const unsigned tgt = ph * NB;
        while (*(volatile unsigned*)&g_bar < tgt) __nanosleep(64);
        __threadfence();
    }
    __syncthreads();
}

__device__ __forceinline__ unsigned upd(int r, int i, bool sel,
                                        float i1, float i2, float i3) {
    if (r == 0) {
        if (sel) {
            float s = tanhf(__ldcg(&g_y1[i]) * i1);
            g_prod[i] = s;
            unsigned nk = f2key(s * __ldcg(&g_y2[i]));
            g_key[i] = nk;
            return nk;
        }
        g_key[i] = 0u; return 0u;
    } else if (r == 1) {
        if (sel) {
            float p = __ldcg(&g_prod[i]);
            float s = tanhf(p * __ldcg(&g_y2[i]) * i2);
            p *= s;
            g_prod[i] = p;
            unsigned nk = f2key(p * __ldcg(&g_y3[i]));
            g_key[i] = nk;
            return nk;
        }
        g_key[i] = 0u; return 0u;
    } else {
        float cf = 0.f;
        if (sel) {
            float p = __ldcg(&g_prod[i]);
            float s = tanhf(p * __ldcg(&g_y3[i]) * i3);
            cf = p * s * (1.0f / 12500.0f);
        }
        g_coef[i] = cf;
        return 0u;
    }
}

extern __shared__ float dsm[];   // [ws1|ws2|ws3 (4332 f)][stages 8*6016 f]

__global__ void __launch_bounds__(NT, 1) k_persist(
    const float* __restrict__ x,
    const float* __restrict__ w1, const float* __restrict__ w2,
    const float* __restrict__ w3, float* __restrict__ out)
{
    const int tid  = threadIdx.x, bid = blockIdx.x;
    const int lane = tid & 31,    wid = tid >> 5;
    const int gtid = bid * NT + tid;
    const int p    = bid & 3;                  // alignment phase of this block
    const int wp   = (bid >> 2) * NWARP + wid; // gather warp id within phase
    const int wg4  = (bid >> 2) * 4 + wid;     // GEMV warp id within phase (wid<4)

    float* ws1 = dsm;
    float* ws2 = dsm + WOFF;
    float* ws3 = dsm + 2 * WOFF;
    float* stg = dsm + WS_FLOATS;              // [8 stages][6016]

    __shared__ float    s_n[3][NWARP];
    __shared__ float    s_inv[3];
    __shared__ unsigned s_scan[256];
    __shared__ unsigned s_Bsel;
    __shared__ int      s_needB;
    __shared__ int      s_cb, s_nr;
    __shared__ __align__(8) uint64_t s_mb[4][2];

    // ---- w norms ----
    {
        float a0 = 0.f, a1 = 0.f, a2 = 0.f;
        for (int i = tid; i < DIMS; i += NT) {
            float v1 = __ldg(w1 + i), v2 = __ldg(w2 + i), v3 = __ldg(w3 + i);
            a0 += v1 * v1; a1 += v2 * v2; a2 += v3 * v3;
        }
#pragma unroll
        for (int off = 16; off > 0; off >>= 1) {
            a0 += __shfl_down_sync(0xffffffffu, a0, off);
            a1 += __shfl_down_sync(0xffffffffu, a1, off);
            a2 += __shfl_down_sync(0xffffffffu, a2, off);
        }
        if (lane == 0) { s_n[0][wid] = a0; s_n[1][wid] = a1; s_n[2][wid] = a2; }
    }
    // ---- p-shifted w copies; mbar init; counters ----
    for (int j = tid; j < 1440; j += NT) {
        ws1[j] = __ldg(w1 + p + j);
        ws2[j] = __ldg(w2 + p + j);
        ws3[j] = __ldg(w3 + p + j);
    }
    if (tid < 8) {
        mb_init(s2u(&s_mb[tid >> 1][tid & 1]), 1);
        fence_async();
    }
    if (bid == 0 && tid < 3) g_ncand3[tid] = 0;
    __syncthreads();
    if (tid < 3) {
        float s = 0.f;
        for (int w = 0; w < NWARP; w++) s += s_n[tid][w];
        s_inv[tid] = 1.0f / sqrtf(s);
    }
    __syncthreads();
    const float i1 = s_inv[0], i2 = s_inv[1], i3 = s_inv[2];

    // ---------------- phase B: row-per-lane GEMV, TMA bulk ring ----------------
    if (wid < 4) {
        // edge columns (block-constant)
        int   ec[3]; float we1[3], we2[3], we3[3];
#pragma unroll
        for (int e = 0; e < 3; e++) {
            ec[e] = (e < p) ? e : p + 1440 + (e - p);
            we1[e] = __ldg(w1 + ec[e]); we2[e] = __ldg(w2 + ec[e]); we3[e] = __ldg(w3 + ec[e]);
        }
        const int ngroups = (NGRP - wg4 + GW4 - 1) / GW4;
        const int ntiles = ngroups * 8;
        const uint32_t mbA[2] = { s2u(&s_mb[wid][0]), s2u(&s_mb[wid][1]) };
        const uint32_t stB = s2u(stg) + (uint32_t)(wid * 2) * (STAGEF * 4)
                           + (uint32_t)lane * (SROW * 4);

        auto issue = [&](int ti) {
            const int slot = ti & 1;
            const int g = wg4 + GW4 * (ti >> 3);
            const int c = ti & 7;
            int j = 32 * g + lane; if (j > JROWS - 1) j = JROWS - 1;
            const float* src = x + (size_t)(p + 4 * j) * DIMS + p + 180 * c;
            if (lane == 0) mb_extx(mbA[slot], TILETX);
            bulk_g2s(stB + (uint32_t)slot * (STAGEF * 4), src, CHUNKB, mbA[slot]);
        };
        issue(0); issue(1);

        int phs[2] = { 0, 0 };
        float a0x=0,a0y=0,a0z=0,a0w=0, a1x=0,a1y=0,a1z=0,a1w=0, a2x=0,a2y=0,a2z=0,a2w=0;
        for (int ti = 0; ti < ntiles; ti++) {
            const int slot = ti & 1;
            const int c = ti & 7;
            const int g = wg4 + GW4 * (ti >> 3);
            if (c == 0) {
                a0x=a0y=a0z=a0w=0; a1x=a1y=a1z=a1w=0; a2x=a2y=a2z=a2w=0;
            }
            mb_wait(mbA[slot], phs[slot]); phs[slot] ^= 1;
            const float4* sb = (const float4*)(stg + (wid * 2 + slot) * STAGEF
                                               + lane * SROW);
            const float4* b1 = (const float4*)(ws1 + 180 * c);
            const float4* b2 = (const float4*)(ws2 + 180 * c);
            const float4* b3 = (const float4*)(ws3 + 180 * c);
#pragma unroll 9
            for (int s = 0; s < 45; s++) {
                float4 xv = sb[s];
                float4 u = b1[s], v = b2[s], w = b3[s];
                a0x += xv.x * u.x; a0y += xv.y * u.y; a0z += xv.z * u.z; a0w += xv.w * u.w;
                a1x += xv.x * v.x; a1y += xv.y * v.y; a1z += xv.z * v.z; a1w += xv.w * v.w;
                a2x += xv.x * w.x; a2y += xv.y * w.y; a2z += xv.z * w.z; a2w += xv.w * w.w;
            }
            fence_async();                    // own reads before own slot reuse
            if (ti + 2 < ntiles) issue(ti + 2);
            if (c == 7) {
                int j = 32 * g + lane;
                if (j < JROWS) {
                    int row = p + 4 * j;
                    float y1 = (a0x + a0y) + (a0z + a0w);
                    float y2 = (a1x + a1y) + (a1z + a1w);
                    float y3 = (a2x + a2y) + (a2z + a2w);
                    const float* rx = x + (size_t)row * DIMS;
#pragma unroll
                    for (int e = 0; e < 3; e++) {
                        float xe = __ldg(rx + ec[e]);
                        y1 += xe * we1[e]; y2 += xe * we2[e]; y3 += xe * we3[e];
                    }
                    g_y1[row] = y1; g_y2[row] = y2; g_y3[row] = y3;
                    unsigned key = f2key(y1);
                    g_key[row] = key;
                    atomicAdd(&g_hist[0][key >> 16], 1u);
                    atomicAdd(&g_hist8[0][key >> 24], 1u);
                }
            }
        }
    }
    unsigned ph = 0;
    gbar(++ph);

    // candidate staging aliases the (now idle) stage area
    unsigned* s_ck = (unsigned*)stg;
    int*      s_cr = (int*)(stg + SCAP);

    // ---------------- selection rounds (2 barriers each) ----------------
    for (int r = 0; r < 3; r++) {
        const int need = (r == 0) ? 50000 : ((r == 1) ? 25000 : 12500);
        unsigned* hist = g_hist[r];

        // C2: two-level scan in EVERY block
        {
            unsigned own = 0;
            if (tid < 256) {
                own = __ldcg(&g_hist8[r][255 - tid]);
                s_scan[tid] = own;
            }
            __syncthreads();
#pragma unroll
            for (int off = 1; off < 256; off <<= 1) {
                unsigned v = (tid >= off && tid < 256) ? s_scan[tid - off] : 0u;
                __syncthreads();
                if (tid < 256) s_scan[tid] += v;
                __syncthreads();
            }
            if (tid < 256) {
                unsigned incl = s_scan[tid], excl = incl - own;
                if ((int)excl < need && need <= (int)incl) {
                    s_cb = 255 - tid;
                    s_nr = need - (int)excl;
                }
            }
            __syncthreads();
            const int cb = s_cb, nr = s_nr;
            unsigned own2 = 0;
            if (tid < 256) {
                own2 = __ldcg(&hist[cb * 256 + 255 - tid]);
                s_scan[tid] = own2;
            }
            __syncthreads();
#pragma unroll
            for (int off = 1; off < 256; off <<= 1) {
                unsigned v = (tid >= off && tid < 256) ? s_scan[tid - off] : 0u;
                __syncthreads();
                if (tid < 256) s_scan[tid] += v;
                __syncthreads();
            }
            if (tid < 256) {
                unsigned incl = s_scan[tid], excl = incl - own2;
                if ((int)excl < nr && nr <= (int)incl) {
                    s_Bsel = (unsigned)(cb * 256 + 255 - tid);
                    s_needB = nr - (int)excl;
                }
            }
            __syncthreads();
        }

        // C3: classify + next-round hists + boundary candidates
        {
            const unsigned Bv = s_Bsel;
            for (int i = gtid; i < NROWS; i += GSTRIDE) {
                unsigned key = __ldcg(&g_key[i]);
                if (key) {
                    unsigned b = key >> 16;
                    if (b > Bv) {
                        unsigned nk = upd(r, i, true, i1, i2, i3);
                        if (r < 2) {
                            atomicAdd(&g_hist[r + 1][nk >> 16], 1u);
                            atomicAdd(&g_hist8[r + 1][nk >> 24], 1u);
                        }
                    } else if (b == Bv) {
                        int ci = atomicAdd(&g_ncand3[r], 1);
                        g_candk[ci] = key; g_candr[ci] = i;
                    } else {
                        upd(r, i, false, i1, i2, i3);
                    }
                } else {
                    upd(r, i, false, i1, i2, i3);
                }
            }
        }
        gbar(++ph);

        // C4: rank boundary candidates; re-zero hists
        {
            for (int i = gtid; i < 65536; i += GSTRIDE) hist[i] = 0u;
            if (bid == 0 && tid < 256) g_hist8[r][tid] = 0u;
            int m  = __ldcg(&g_ncand3[r]);
            int nB = s_needB;
            int mc = (m < SCAP) ? m : SCAP;
            for (int j = tid; j < mc; j += NT) {
                s_ck[j] = __ldcg(&g_candk[j]);
                s_cr[j] = __ldcg(&g_candr[j]);
            }
            __syncthreads();
            for (int ci = gtid; ci < m; ci += GSTRIDE) {
                unsigned mk = (ci < mc) ? s_ck[ci] : __ldcg(&g_candk[ci]);
                int      mr = (ci < mc) ? s_cr[ci] : __ldcg(&g_candr[ci]);
                int cnt = 0;
                for (int j = 0; j < mc; j++) {
                    unsigned kj = s_ck[j]; int rj = s_cr[j];
                    cnt += (kj > mk || (kj == mk && rj < mr)) ? 1 : 0;
                }
                for (int j = mc; j < m; j++) {
                    unsigned kj = __ldcg(&g_candk[j]); int rj = __ldcg(&g_candr[j]);
                    cnt += (kj > mk || (kj == mk && rj < mr)) ? 1 : 0;
                }
                bool sel = (cnt < nB);
                unsigned nk = upd(r, mr, sel, i1, i2, i3);
                if (r < 2 && sel) {
                    atomicAdd(&g_hist[r + 1][nk >> 16], 1u);
                    atomicAdd(&g_hist8[r + 1][nk >> 24], 1u);
                }
            }
            __syncthreads();   // s_ck reuse next round
        }
        gbar(++ph);
    }

    // ---------------- phase D: gather + block smem reduction ----------------
    {
        const int e = lane - 8;
        const bool haveE = (e >= 0 && e < 3);
        const int ecol = haveE ? ((e < p) ? e : p + 1440 + (e - p)) : 0;
        const int m11 = 352 + lane;
        const bool l8 = (lane < 8);
        float4 acc[12];
#pragma unroll
        for (int kk = 0; kk < 12; kk++) acc[kk] = make_float4(0.f, 0.f, 0.f, 0.f);
        float accE = 0.f;
        for (int jj = wp; jj < JROWS; jj += WPP) {
            int row = p + 4 * jj;
            float c = __ldcg(&g_coef[row]);
            if (c == 0.0f) continue;
            const float4* px = (const float4*)(x + (size_t)row * DIMS + p);
#pragma unroll
            for (int k = 0; k < 11; k++) {
                float4 v = __ldg(px + lane + 32 * k);
                acc[k].x += c * v.x; acc[k].y += c * v.y;
                acc[k].z += c * v.z; acc[k].w += c * v.w;
            }
            if (l8) {
                float4 v = __ldg(px + m11);
                acc[11].x += c * v.x; acc[11].y += c * v.y;
                acc[11].z += c * v.z; acc[11].w += c * v.w;
            }
            if (haveE) accE += c * __ldg(x + (size_t)row * DIMS + ecol);
        }
        float* sa = stg + wid * WOFF;   // gather staging aliases stage area
#pragma unroll
        for (int k = 0; k < 12; k++) {
            if (k < 11 || l8) {
                int m = (k < 11) ? (lane + 32 * k) : m11;
                int cb = p + 4 * m;
                sa[cb] = acc[k].x; sa[cb + 1] = acc[k].y;
                sa[cb + 2] = acc[k].z; sa[cb + 3] = acc[k].w;
            }
        }
        if (haveE) sa[ecol] = accE;
        __syncthreads();
        for (int col = tid; col < DIMS; col += NT) {
            float s = 0.f;
#pragma unroll
            for (int w = 0; w < NWARP; w++) s += stg[w * WOFF + col];
            g_fpart[bid][col] = s;
        }
    }
    gbar(++ph);

    // ---------------- E: reduce 148 block partials -> out ----------------
    if (bid * NWARP + wid < 46) {
        int col = (bid * NWARP + wid) * 32 + lane;
        if (col < DIMS) {
            float s = 0.f;
#pragma unroll 8
            for (int j = 0; j < NB; j++) s += __ldcg(&g_fpart[j][col]);
            out[col] = s;
        }
    }

    // ---- final arrive-only barrier; block 0 resets counter ----
    __syncthreads();
    if (tid == 0) {
        __threadfence();
        const unsigned tgt = (ph + 1) * NB;
        atomicAdd(&g_bar, 1u);
        if (bid == 0) {
            while (*(volatile unsigned*)&g_bar < tgt) __nanosleep(64);
            atomicExch(&g_bar, 0u);
            __threadfence();
        }
    }
}

// ---------------- launch ----------------
extern "C" void kernel_launch(void* const* d_in, const int* in_sizes, int n_in,
                              void* d_out, int out_size) {
    const float* x  = (const float*)d_in[0];
    // d_in[1] edge_index, d_in[2] edge_attr: dead inputs
    const float* w1 = (const float*)d_in[3];
    const float* w2 = (const float*)d_in[4];
    const float* w3 = (const float*)d_in[5];
    float* out = (float*)d_out;

    cudaFuncSetAttribute(k_persist, cudaFuncAttributeMaxDynamicSharedMemorySize,
                         DSMEM);
    k_persist<<<NB, NT, DSMEM>>>(x, w1, w2, w3, out);
}

// round 16
// speedup vs baseline: 1.0376x; 1.0376x over previous
#include <cuda_runtime.h>
#include <math.h>
#include <stdint.h>

#define NROWS 100000
#define DIMS  1443
#define NB    148
#define NT    512
#define NWARP 16
#define GSTRIDE (NB*NT)
#define WPP   (37*NWARP)        // 592 gather warps per phase
#define JROWS 25000
#define SCAP  1024
#define GWRP  8                 // GEMV warps per block
#define NPAIR 12500             // row pairs per phase
#define WPG   (37*GWRP)         // 296 GEMV warps per phase
#define ROWFB 1440              // floats copied per row
#define ROWB  5760              // bytes per row copy
#define PAIRB (2*ROWB)          // 11520 per tile
#define WPACK_BYTES (3*360*16)                  // 17280
#define STAGE_BYTES (GWRP*2*PAIRB)              // 184320
#define DSMEM (WPACK_BYTES + STAGE_BYTES)       // 201600
#define ACCW  1444

// ---------------- device scratch (allocation-free) ----------------
__device__ unsigned g_bar = 0;
__device__ float    g_y1[NROWS], g_y2[NROWS], g_y3[NROWS];
__device__ float    g_prod[NROWS];
__device__ float    g_coef[NROWS];
__device__ unsigned g_key[NROWS];
__device__ unsigned g_hist[3][65536];     // zeroed in C4 of its round (replay invariant)
__device__ unsigned g_hist8[3][256];
__device__ unsigned g_candk[NROWS];
__device__ int      g_candr[NROWS];
__device__ int      g_ncand3[3];
__device__ float    g_fpart[NB][DIMS];

__device__ __forceinline__ unsigned f2key(float f) {
    unsigned u = __float_as_uint(f);
    return (u & 0x80000000u) ? ~u : (u | 0x80000000u);
}
__device__ __forceinline__ uint32_t s2u(const void* p) {
    uint32_t a;
    asm("{ .reg .u64 t; cvta.to.shared.u64 t, %1; cvt.u32.u64 %0, t; }"
        : "=r"(a) : "l"(p));
    return a;
}
__device__ __forceinline__ void mb_init(uint32_t m, uint32_t c) {
    asm volatile("mbarrier.init.shared.b64 [%0], %1;" :: "r"(m), "r"(c) : "memory");
}
__device__ __forceinline__ void mb_extx(uint32_t m, uint32_t b) {
    asm volatile("mbarrier.arrive.expect_tx.shared.b64 _, [%0], %1;"
                 :: "r"(m), "r"(b) : "memory");
}
__device__ __forceinline__ void bulk_g2s(uint32_t dst, const void* src,
                                         uint32_t bytes, uint32_t m) {
    asm volatile("cp.async.bulk.shared::cta.global.mbarrier::complete_tx::bytes "
                 "[%0], [%1], %2, [%3];"
                 :: "r"(dst), "l"(src), "r"(bytes), "r"(m) : "memory");
}
__device__ __forceinline__ void mb_wait(uint32_t m, uint32_t par) {
    uint32_t done;
    asm volatile(
        "{ .reg .pred p; mbarrier.try_wait.parity.acquire.cta.shared::cta.b64 "
        "p, [%1], %2; selp.b32 %0,1,0,p; }"
        : "=r"(done) : "r"(m), "r"(par) : "memory");
    while (!done) {
        asm volatile(
            "{ .reg .pred p; mbarrier.try_wait.parity.acquire.cta.shared::cta.b64 "
            "p, [%1], %2, 0x989680; selp.b32 %0,1,0,p; }"
            : "=r"(done) : "r"(m), "r"(par) : "memory");
    }
}
__device__ __forceinline__ void fence_async() {
    asm volatile("fence.proxy.async.shared::cta;" ::: "memory");
}

// grid barrier: arrive via atomicAdd, spin on plain volatile load
__device__ __forceinline__ void gbar(unsigned ph) {
    __syncthreads();
    if (threadIdx.x == 0) {
        __threadfence();
        atomicAdd(&g_bar, 1u);
        const unsigned tgt = ph * NB;
        while (*(volatile unsigned*)&g_bar < tgt) __nanosleep(64);
        __threadfence();
    }
    __syncthreads();
}

__device__ __forceinline__ unsigned upd(int r, int i, bool sel,
                                        float i1, float i2, float i3) {
    if (r == 0) {
        if (sel) {
            float s = tanhf(__ldcg(&g_y1[i]) * i1);
            g_prod[i] = s;
            unsigned nk = f2key(s * __ldcg(&g_y2[i]));
            g_key[i] = nk;
            return nk;
        }
        g_key[i] = 0u; return 0u;
    } else if (r == 1) {
        if (sel) {
            float p = __ldcg(&g_prod[i]);
            float s = tanhf(p * __ldcg(&g_y2[i]) * i2);
            p *= s;
            g_prod[i] = p;
            unsigned nk = f2key(p * __ldcg(&g_y3[i]));
            g_key[i] = nk;
            return nk;
        }
        g_key[i] = 0u; return 0u;
    } else {
        float cf = 0.f;
        if (sel) {
            float p = __ldcg(&g_prod[i]);
            float s = tanhf(p * __ldcg(&g_y3[i]) * i3);
            cf = p * s * (1.0f / 12500.0f);
        }
        g_coef[i] = cf;
        return 0u;
    }
}

extern __shared__ float dsm[];   // [w-pack 4320 f][stages 46080 f]

__global__ void __launch_bounds__(NT, 1) k_persist(
    const float* __restrict__ x,
    const float* __restrict__ w1, const float* __restrict__ w2,
    const float* __restrict__ w3, float* __restrict__ out)
{
    const int tid  = threadIdx.x, bid = blockIdx.x;
    const int lane = tid & 31,    wid = tid >> 5;
    const int gtid = bid * NT + tid;
    const int p    = bid & 3;                  // alignment phase of this block
    const int wp   = (bid >> 2) * NWARP + wid; // gather warp id within phase
    const int wg8  = (bid >> 2) * GWRP + wid;  // GEMV warp id within phase (wid<8)

    float4* s_wp = (float4*)dsm;               // [3][360]
    float*  stg  = dsm + 3 * 360 * 4;          // stage area (46080 floats)

    __shared__ float    s_n[3][NWARP];
    __shared__ float    s_inv[3];
    __shared__ unsigned s_scan[256];
    __shared__ unsigned s_ck[SCAP];
    __shared__ int      s_cr[SCAP];
    __shared__ unsigned s_Bsel;
    __shared__ int      s_needB;
    __shared__ int      s_cb, s_nr;
    __shared__ __align__(8) uint64_t s_mb[GWRP][2];

    // ---- w norms ----
    {
        float a0 = 0.f, a1 = 0.f, a2 = 0.f;
        for (int i = tid; i < DIMS; i += NT) {
            float v1 = __ldg(w1 + i), v2 = __ldg(w2 + i), v3 = __ldg(w3 + i);
            a0 += v1 * v1; a1 += v2 * v2; a2 += v3 * v3;
        }
#pragma unroll
        for (int off = 16; off > 0; off >>= 1) {
            a0 += __shfl_down_sync(0xffffffffu, a0, off);
            a1 += __shfl_down_sync(0xffffffffu, a1, off);
            a2 += __shfl_down_sync(0xffffffffu, a2, off);
        }
        if (lane == 0) { s_n[0][wid] = a0; s_n[1][wid] = a1; s_n[2][wid] = a2; }
    }
    // ---- fill phase-local w-pack; init mbarriers; zero counters ----
    for (int idx = tid; idx < 3 * 360; idx += NT) {
        int v = idx / 360, m = idx % 360;
        const float* w = (v == 0) ? w1 : ((v == 1) ? w2 : w3);
        int col = p + 4 * m;
        s_wp[idx] = make_float4(__ldg(w + col), __ldg(w + col + 1),
                                __ldg(w + col + 2), __ldg(w + col + 3));
    }
    if (tid < GWRP * 2) {
        mb_init(s2u(&s_mb[tid >> 1][tid & 1]), 1);
        fence_async();
    }
    if (bid == 0 && tid < 3) g_ncand3[tid] = 0;
    __syncthreads();
    if (tid < 3) {
        float s = 0.f;
        for (int w = 0; w < NWARP; w++) s += s_n[tid][w];
        s_inv[tid] = 1.0f / sqrtf(s);
    }
    __syncthreads();
    const float i1 = s_inv[0], i2 = s_inv[1], i3 = s_inv[2];

    // ---------------- phase B: GEMV, 2 rows per tile, TMA bulk ring ----------------
    if (wid < GWRP) {
        const float4* wpa = s_wp;
        const float4* wpb = s_wp + 360;
        const float4* wpc = s_wp + 720;
        const int e = lane - 8;
        const bool haveE = (e >= 0 && e < 3);
        int ecol = 0; float we1 = 0.f, we2 = 0.f, we3 = 0.f;
        if (haveE) {
            ecol = (e < p) ? e : p + 1440 + (e - p);
            we1 = __ldg(w1 + ecol); we2 = __ldg(w2 + ecol); we3 = __ldg(w3 + ecol);
        }
        const int  m11 = (lane < 8) ? (352 + lane) : 359;   // safe in-row dup
        const bool l8  = (lane < 8);
        const uint32_t stB = s2u(stg) + (uint32_t)(wid * 2) * PAIRB;
        const uint32_t mbA[2] = { s2u(&s_mb[wid][0]), s2u(&s_mb[wid][1]) };

        auto issuePair = [&](int q, int slot) {
            if (q < NPAIR && lane == 0) {
                int r0 = p + 8 * q;
                uint32_t dst = stB + (uint32_t)slot * PAIRB;
                mb_extx(mbA[slot], PAIRB);
                bulk_g2s(dst,        x + (size_t)r0 * DIMS + p,       ROWB, mbA[slot]);
                bulk_g2s(dst + ROWB, x + (size_t)(r0 + 4) * DIMS + p, ROWB, mbA[slot]);
            }
        };
        issuePair(wg8, 0);
        issuePair(wg8 + WPG, 1);

        int phs0 = 0, phs1 = 0, t = 0;
        for (int q = wg8; q < NPAIR; q += WPG, ++t) {
            const int slot = t & 1;
            const int r0 = p + 8 * q, r1 = r0 + 4;
            float xe0 = 0.f, xe1 = 0.f;
            if (haveE) {
                xe0 = __ldcg(x + (size_t)r0 * DIMS + ecol);
                xe1 = __ldcg(x + (size_t)r1 * DIMS + ecol);
            }
            if (slot == 0) { mb_wait(mbA[0], phs0); phs0 ^= 1; }
            else           { mb_wait(mbA[1], phs1); phs1 ^= 1; }
            const float4* rb0 = (const float4*)(stg + (wid * 2 + slot) * (2 * ROWFB));
            const float4* rb1 = rb0 + 360;
            float a0 = 0.f, a1 = 0.f, a2 = 0.f, a3 = 0.f, a4 = 0.f, a5 = 0.f;
#pragma unroll 4
            for (int k = 0; k < 12; k++) {
                const int m = (k < 11) ? (lane + 32 * k) : m11;
                float4 wa = wpa[m], wb = wpb[m], wc = wpc[m];
                if (k == 11 && !l8) {
                    wa = make_float4(0.f, 0.f, 0.f, 0.f); wb = wa; wc = wa;
                }
                float4 v0 = rb0[m], v1 = rb1[m];
                a0 += v0.x*wa.x + v0.y*wa.y + v0.z*wa.z + v0.w*wa.w;
                a1 += v0.x*wb.x + v0.y*wb.y + v0.z*wb.z + v0.w*wb.w;
                a2 += v0.x*wc.x + v0.y*wc.y + v0.z*wc.z + v0.w*wc.w;
                a3 += v1.x*wa.x + v1.y*wa.y + v1.z*wa.z + v1.w*wa.w;
                a4 += v1.x*wb.x + v1.y*wb.y + v1.z*wb.z + v1.w*wb.w;
                a5 += v1.x*wc.x + v1.y*wc.y + v1.z*wc.z + v1.w*wc.w;
            }
            if (haveE) {
                a0 += xe0 * we1; a1 += xe0 * we2; a2 += xe0 * we3;
                a3 += xe1 * we1; a4 += xe1 * we2; a5 += xe1 * we3;
            }
            fence_async();                 // order smem reads before async reuse
            __syncwarp();                  // all lanes' fences precede lane0 re-issue
            issuePair(q + 2 * WPG, slot);  // refill slot
#pragma unroll
            for (int off = 16; off > 0; off >>= 1) {
                a0 += __shfl_down_sync(0xffffffffu, a0, off);
                a1 += __shfl_down_sync(0xffffffffu, a1, off);
                a2 += __shfl_down_sync(0xffffffffu, a2, off);
                a3 += __shfl_down_sync(0xffffffffu, a3, off);
                a4 += __shfl_down_sync(0xffffffffu, a4, off);
                a5 += __shfl_down_sync(0xffffffffu, a5, off);
            }
            if (lane == 0) {
                g_y1[r0] = a0; g_y2[r0] = a1; g_y3[r0] = a2;
                unsigned k0 = f2key(a0);
                g_key[r0] = k0;
                atomicAdd(&g_hist[0][k0 >> 16], 1u);
                atomicAdd(&g_hist8[0][k0 >> 24], 1u);
                g_y1[r1] = a3; g_y2[r1] = a4; g_y3[r1] = a5;
                unsigned k1 = f2key(a3);
                g_key[r1] = k1;
                atomicAdd(&g_hist[0][k1 >> 16], 1u);
                atomicAdd(&g_hist8[0][k1 >> 24], 1u);
            }
        }
    }
    unsigned ph = 0;
    gbar(++ph);

    // ---------------- selection rounds (2 barriers each) ----------------
    for (int r = 0; r < 3; r++) {
        const int need = (r == 0) ? 50000 : ((r == 1) ? 25000 : 12500);
        unsigned* hist = g_hist[r];

        // C2: two-level scan in EVERY block (512 bin reads total)
        {
            unsigned own = 0;
            if (tid < 256) {
                own = __ldcg(&g_hist8[r][255 - tid]);
                s_scan[tid] = own;
            }
            __syncthreads();
#pragma unroll
            for (int off = 1; off < 256; off <<= 1) {
                unsigned v = (tid >= off && tid < 256) ? s_scan[tid - off] : 0u;
                __syncthreads();
                if (tid < 256) s_scan[tid] += v;
                __syncthreads();
            }
            if (tid < 256) {
                unsigned incl = s_scan[tid], excl = incl - own;
                if ((int)excl < need && need <= (int)incl) {
                    s_cb = 255 - tid;
                    s_nr = need - (int)excl;
                }
            }
            __syncthreads();
            const int cb = s_cb, nr = s_nr;
            unsigned own2 = 0;
            if (tid < 256) {
                own2 = __ldcg(&hist[cb * 256 + 255 - tid]);
                s_scan[tid] = own2;
            }
            __syncthreads();
#pragma unroll
            for (int off = 1; off < 256; off <<= 1) {
                unsigned v = (tid >= off && tid < 256) ? s_scan[tid - off] : 0u;
                __syncthreads();
                if (tid < 256) s_scan[tid] += v;
                __syncthreads();
            }
            if (tid < 256) {
                unsigned incl = s_scan[tid], excl = incl - own2;
                if ((int)excl < nr && nr <= (int)incl) {
                    s_Bsel = (unsigned)(cb * 256 + 255 - tid);
                    s_needB = nr - (int)excl;
                }
            }
            __syncthreads();
        }

        // C3: classify + next-round hists + boundary candidates
        {
            const unsigned Bv = s_Bsel;
            for (int i = gtid; i < NROWS; i += GSTRIDE) {
                unsigned key = __ldcg(&g_key[i]);
                if (key) {
                    unsigned b = key >> 16;
                    if (b > Bv) {
                        unsigned nk = upd(r, i, true, i1, i2, i3);
                        if (r < 2) {
                            atomicAdd(&g_hist[r + 1][nk >> 16], 1u);
                            atomicAdd(&g_hist8[r + 1][nk >> 24], 1u);
                        }
                    } else if (b == Bv) {
                        int ci = atomicAdd(&g_ncand3[r], 1);
                        g_candk[ci] = key; g_candr[ci] = i;
                    } else {
                        upd(r, i, false, i1, i2, i3);
                    }
                } else {
                    upd(r, i, false, i1, i2, i3);   // writes coef=0 when r==2
                }
            }
        }
        gbar(++ph);

        // C4: rank boundary candidates; re-zero hists (replay invariant)
        {
            for (int i = gtid; i < 65536; i += GSTRIDE) hist[i] = 0u;
            if (bid == 0 && tid < 256) g_hist8[r][tid] = 0u;
            int m  = __ldcg(&g_ncand3[r]);
            int nB = s_needB;
            int mc = (m < SCAP) ? m : SCAP;
            for (int j = tid; j < mc; j += NT) {
                s_ck[j] = __ldcg(&g_candk[j]);
                s_cr[j] = __ldcg(&g_candr[j]);
            }
            __syncthreads();
            for (int ci = gtid; ci < m; ci += GSTRIDE) {
                unsigned mk = (ci < mc) ? s_ck[ci] : __ldcg(&g_candk[ci]);
                int      mr = (ci < mc) ? s_cr[ci] : __ldcg(&g_candr[ci]);
                int cnt = 0;
                for (int j = 0; j < mc; j++) {
                    unsigned kj = s_ck[j]; int rj = s_cr[j];
                    cnt += (kj > mk || (kj == mk && rj < mr)) ? 1 : 0;
                }
                for (int j = mc; j < m; j++) {
                    unsigned kj = __ldcg(&g_candk[j]); int rj = __ldcg(&g_candr[j]);
                    cnt += (kj > mk || (kj == mk && rj < mr)) ? 1 : 0;
                }
                bool sel = (cnt < nB);
                unsigned nk = upd(r, mr, sel, i1, i2, i3);
                if (r < 2 && sel) {
                    atomicAdd(&g_hist[r + 1][nk >> 16], 1u);
                    atomicAdd(&g_hist8[r + 1][nk >> 24], 1u);
                }
            }
        }
        gbar(++ph);
    }

    // ---------------- phase D: gather + block smem reduction ----------------
    {
        const int e = lane - 8;
        const bool haveE = (e >= 0 && e < 3);
        const int ecol = haveE ? ((e < p) ? e : p + 1440 + (e - p)) : 0;
        const int m11 = 352 + lane;
        const bool l8 = (lane < 8);
        float4 acc[12];
#pragma unroll
        for (int kk = 0; kk < 12; kk++) acc[kk] = make_float4(0.f, 0.f, 0.f, 0.f);
        float accE = 0.f;
        for (int jj = wp; jj < JROWS; jj += WPP) {
            int row = p + 4 * jj;
            float c = __ldcg(&g_coef[row]);
            if (c == 0.0f) continue;
            const float4* px = (const float4*)(x + (size_t)row * DIMS + p);
#pragma unroll
            for (int k = 0; k < 11; k++) {
                float4 v = __ldg(px + lane + 32 * k);
                acc[k].x += c * v.x; acc[k].y += c * v.y;
                acc[k].z += c * v.z; acc[k].w += c * v.w;
            }
            if (l8) {
                float4 v = __ldg(px + m11);
                acc[11].x += c * v.x; acc[11].y += c * v.y;
                acc[11].z += c * v.z; acc[11].w += c * v.w;
            }
            if (haveE) accE += c * __ldg(x + (size_t)row * DIMS + ecol);
        }
        float* sa = stg + wid * ACCW;   // stage area is free now
#pragma unroll
        for (int k = 0; k < 12; k++) {
            if (k < 11 || l8) {
                int m = (k < 11) ? (lane + 32 * k) : m11;
                int cb = p + 4 * m;
                sa[cb] = acc[k].x; sa[cb + 1] = acc[k].y;
                sa[cb + 2] = acc[k].z; sa[cb + 3] = acc[k].w;
            }
        }
        if (haveE) sa[ecol] = accE;
        __syncthreads();
        for (int col = tid; col < DIMS; col += NT) {
            float s = 0.f;
#pragma unroll
            for (int w = 0; w < NWARP; w++) s += stg[w * ACCW + col];
            g_fpart[bid][col] = s;
        }
    }
    gbar(++ph);

    // ---------------- E: reduce 148 block partials -> out ----------------
    if (bid * NWARP + wid < 46) {
        int col = (bid * NWARP + wid) * 32 + lane;
        if (col < DIMS) {
            float s = 0.f;
#pragma unroll 8
            for (int j = 0; j < NB; j++) s += __ldcg(&g_fpart[j][col]);
            out[col] = s;
        }
    }

    // ---- final arrive-only barrier; block 0 resets counter ----
    __syncthreads();
    if (tid == 0) {
        __threadfence();
        const unsigned tgt = (ph + 1) * NB;
        atomicAdd(&g_bar, 1u);
        if (bid == 0) {
            while (*(volatile unsigned*)&g_bar < tgt) __nanosleep(64);
            atomicExch(&g_bar, 0u);
            __threadfence();
        }
    }
}

// ---------------- launch ----------------
extern "C" void kernel_launch(void* const* d_in, const int* in_sizes, int n_in,
                              void* d_out, int out_size) {
    const float* x  = (const float*)d_in[0];
    // d_in[1] edge_index, d_in[2] edge_attr: dead inputs
    const float* w1 = (const float*)d_in[3];
    const float* w2 = (const float*)d_in[4];
    const float* w3 = (const float*)d_in[5];
    float* out = (float*)d_out;

    cudaFuncSetAttribute(k_persist, cudaFuncAttributeMaxDynamicSharedMemorySize,
                         DSMEM);
    k_persist<<<NB, NT, DSMEM>>>(x, w1, w2, w3, out);
}